// round 6
// baseline (speedup 1.0000x reference)
#include <cuda_runtime.h>

#define BATCH_N 262144
#define TPB     128
#define NBLK    (BATCH_N / TPB)   // 2048

__device__ float g_partials[NBLK];
__device__ unsigned int g_count = 0;

// alpha = atan(10*d)/pi + 0.5, minimax degree-11 odd poly, |err| < ~1e-6.
__device__ __forceinline__ float fast_alpha(float d) {
    float z = 10.0f * d;
    float r;
    asm("rcp.approx.f32 %0, %1;" : "=f"(r) : "f"(z));
    bool  big = fabsf(z) > 1.0f;
    float w   = big ? r : z;
    float u   = w * w;
    float q   = -0.003730699f;
    q = fmaf(q, u,  0.016758625f);
    q = fmaf(q, u, -0.037058160f);
    q = fmaf(q, u,  0.061602231f);
    q = fmaf(q, u, -0.105877602f);
    q = fmaf(q, u,  0.318303375f);   // atan(w)/(pi*w)
    q = q * w;                       // atan(w)/pi, signed
    float base = big ? ((z > 0.0f) ? 1.0f : 0.0f) : 0.5f;
    float s    = big ? -1.0f : 1.0f;
    return fmaf(s, q, base);
}

__global__ __launch_bounds__(TPB, 6)
void diffsort_loss_kernel(const float* __restrict__ pred,
                          const float* __restrict__ labels,
                          const float* __restrict__ ema,
                          float* __restrict__ out)
{
    __shared__ float s_ema[8];
    if (threadIdx.x < 8) s_ema[threadIdx.x] = ema[threadIdx.x];
    __syncthreads();

    const int row = blockIdx.x * TPB + threadIdx.x;

    const float4* p4 = reinterpret_cast<const float4*>(pred   + (size_t)row * 8);
    const float4* l4 = reinterpret_cast<const float4*>(labels + (size_t)row * 8);
    float4 pa = p4[0], pb = p4[1];
    float4 la = l4[0], lb = l4[1];

    float pr[8]  = {pa.x, pa.y, pa.z, pa.w, pb.x, pb.y, pb.z, pb.w};
    float lab[8] = {la.x, la.y, la.z, la.w, lb.x, lb.y, lb.z, lb.w};

    // rank_true[i]: descending rank of labels[i], stable tie-break by index.
    // Kept transient: gathered into x, then nibble-packed into one register
    // (rtp) so only 1 reg stays live across the sorting network instead of 8.
    float x[8];
    unsigned int rtp = 0;
    {
        int rt[8] = {0, 0, 0, 0, 0, 0, 0, 0};
        #pragma unroll
        for (int i = 0; i < 8; i++) {
            #pragma unroll
            for (int j = i + 1; j < 8; j++) {
                int c = lab[j] > lab[i];
                rt[i] += c;
                rt[j] += 1 - c;
            }
        }
        #pragma unroll
        for (int i = 0; i < 8; i++) {
            x[i] = s_ema[rt[i]] - pr[i];           // -(pred - ema[rank])
            rtp |= (unsigned int)rt[i] << (4 * i);
        }
    }

    // P in registers, identity
    float P[8][8];
    #pragma unroll
    for (int r = 0; r < 8; r++) {
        #pragma unroll
        for (int c = 0; c < 8; c++) P[r][c] = (r == c) ? 1.0f : 0.0f;
    }

    // comparator on wires (i, i+1); only rows [RLO, RHI] can be nonzero in
    // columns i, i+1 at this point (support-set propagation). UPX=0 skips
    // the dead x-update on the final layer.
#define CPAIR(i, RLO, RHI, UPX) do {                                        \
        float a_ = x[i], b_ = x[(i) + 1];                                   \
        float al_ = fast_alpha(b_ - a_);                                    \
        if (UPX) {                                                          \
            float t_ = a_ - b_;                                             \
            x[i]       = fmaf(al_,  t_, b_);                                \
            x[(i) + 1] = fmaf(-al_, t_, a_);                                \
        }                                                                   \
        _Pragma("unroll")                                                   \
        for (int r_ = (RLO); r_ <= (RHI); r_++) {                           \
            float A_ = P[r_][i], B_ = P[r_][(i) + 1];                       \
            float t2_ = A_ - B_;                                            \
            P[r_][i]       = fmaf(al_,  t2_, B_);                           \
            P[r_][(i) + 1] = fmaf(-al_, t2_, A_);                           \
        }                                                                   \
    } while (0)

    CPAIR(0,0,1,1); CPAIR(2,2,3,1); CPAIR(4,4,5,1); CPAIR(6,6,7,1);  // L0
    CPAIR(1,0,3,1); CPAIR(3,2,5,1); CPAIR(5,4,7,1);                  // L1
    CPAIR(0,0,3,1); CPAIR(2,0,5,1); CPAIR(4,2,7,1); CPAIR(6,4,7,1);  // L2
    CPAIR(1,0,5,1); CPAIR(3,0,7,1); CPAIR(5,2,7,1);                  // L3
    CPAIR(0,0,5,1); CPAIR(2,0,7,1); CPAIR(4,0,7,1); CPAIR(6,2,7,1);  // L4
    CPAIR(1,0,7,1); CPAIR(3,0,7,1); CPAIR(5,0,7,1);                  // L5
    CPAIR(0,0,7,1); CPAIR(2,0,7,1); CPAIR(4,0,7,1); CPAIR(6,0,7,1);  // L6
    CPAIR(1,0,7,0); CPAIR(3,0,7,0); CPAIR(5,0,7,0);                  // L7
#undef CPAIR

    // loss = sum_{ij} log1p(-p) + sum_i [log(p_g) - log1p(-p_g)], g=(i,rt[i]).
    // Logs accumulated in log2 units; ln2 folded into the final scale.
    float s = 0.0f;
    #pragma unroll
    for (int c = 0; c < 8; c += 2) {
        float pe = 1.0f, po = 1.0f;
        #pragma unroll
        for (int r = 0; r < 8; r++) {
            pe = fmaf(-pe, P[r][c],     pe);   // pe *= (1 - P[r][c])
            po = fmaf(-po, P[r][c + 1], po);
        }
        s += __log2f(pe * po);
    }

    #pragma unroll
    for (int i = 0; i < 8; i++) {
        // 3-level bit-select tree for pg = P[i][rt[i]], rt from packed nibbles
        unsigned int ri = rtp >> (4 * i);
        bool b0 = ri & 1u, b1 = ri & 2u, b2 = ri & 4u;
        float s0 = b0 ? P[i][1] : P[i][0];
        float s1 = b0 ? P[i][3] : P[i][2];
        float s2 = b0 ? P[i][5] : P[i][4];
        float s3 = b0 ? P[i][7] : P[i][6];
        float t0 = b1 ? s1 : s0;
        float t1 = b1 ? s3 : s2;
        float pg = b2 ? t1 : t0;
        s += __log2f(pg) - __log2f(1.0f - pg);
    }

    // deterministic block reduction
    #pragma unroll
    for (int o = 16; o > 0; o >>= 1) s += __shfl_xor_sync(0xffffffffu, s, o);
    __shared__ float ws[TPB / 32];
    __shared__ bool s_last;
    if ((threadIdx.x & 31) == 0) ws[threadIdx.x >> 5] = s;
    __syncthreads();
    if (threadIdx.x == 0) {
        float bs = 0.0f;
        #pragma unroll
        for (int w = 0; w < TPB / 32; w++) bs += ws[w];
        g_partials[blockIdx.x] = bs;
        __threadfence();
        unsigned int old = atomicAdd(&g_count, 1u);
        s_last = (old == NBLK - 1);
    }
    __syncthreads();

    // last block performs the deterministic, fixed-order final reduction
    if (s_last) {
        const int t = threadIdx.x;
        double ds = 0.0;
        #pragma unroll
        for (int k = 0; k < NBLK / TPB; k++)
            ds += (double)g_partials[t + k * TPB];
        #pragma unroll
        for (int o = 16; o > 0; o >>= 1) ds += __shfl_xor_sync(0xffffffffu, ds, o);
        __shared__ double wd[TPB / 32];
        if ((t & 31) == 0) wd[t >> 5] = ds;
        __syncthreads();
        if (t == 0) {
            double tot = 0.0;
            #pragma unroll
            for (int w = 0; w < TPB / 32; w++) tot += wd[w];
            // tot is in log2 units: loss = -ln2 * tot / (B*64)
            out[0] = (float)(-tot * 0.6931471805599453
                             / ((double)BATCH_N * 64.0));
            g_count = 0;   // reset for next graph replay
        }
    }
}

extern "C" void kernel_launch(void* const* d_in, const int* in_sizes, int n_in,
                              void* d_out, int out_size)
{
    const float* pred   = (const float*)d_in[0];
    const float* labels = (const float*)d_in[1];
    const float* ema    = (const float*)d_in[2];
    diffsort_loss_kernel<<<NBLK, TPB>>>(pred, labels, ema, (float*)d_out);
}